// round 15
// baseline (speedup 1.0000x reference)
#include <cuda_runtime.h>
#include <cuda_bf16.h>
#include <math_constants.h>

#define B_      8
#define N_      8192
#define S_      2048
#define K_      16
#define DIN_    64
#define DOUT_   128
#define BN_EPS_ 1e-5f

#define FT_     512            // FPS threads (16 warps)
#define PPT_    16             // points per thread per batch
#define NCELL_  2048           // Morton cells: x4,y4,z3 bits

// ---------------- scratch (static __device__ — no allocation allowed) ----------------
__device__ int   g_fps_idx[B_ * S_];
__device__ int   g_knn_idx[B_ * S_ * K_];
__device__ float g_h[B_ * N_ * DOUT_];   // 33.5 MB, post MLP+BN+ReLU features

// 4-bit Morton spread: bits -> positions 0,3,6,9 (setup only)
__device__ __forceinline__ unsigned spread3(unsigned v) {
    return (v & 1u) | ((v & 2u) << 2) | ((v & 4u) << 4) | ((v & 8u) << 6);
}
__device__ __forceinline__ unsigned cell_of(float x, float y, float z) {
    unsigned bx = (unsigned)min(max((int)floorf(x * 2.0f) + 8, 0), 15);
    unsigned by = (unsigned)min(max((int)floorf(y * 2.0f) + 8, 0), 15);
    unsigned bz = (unsigned)min(max((int)floorf(z) + 4, 0), 7);
    return spread3(bx) | (spread3(by) << 1) | (spread3(bz) << 2);   // < 2048
}
// XOR swizzles: conflict-free for thread t reading slots t*16..t*16+15
__device__ __forceinline__ int sw_xy(int s) { return s ^ ((s >> 4) & 15); }  // float2 units
__device__ __forceinline__ int sw_z (int s) { return s ^ ((s >> 4) & 31); }  // float units

// ============================================================================
// 1) FPS — 4 CTAs; each runs TWO independent batches (2k, 2k+1) interleaved
//    in the same warps to fill the 56% issue-stall measured in round 14.
//    Per batch: Morton sort (2048 cells) into XOR-swizzled smem (float2 xy +
//    float z, 12B/pt), orig idx packed into registers; per-thread exact
//    pruning (skip iff lb*0.99999 >= cached max pd — provably bit-exact
//    no-op, identical logic to rounds 8-12); exact IEEE distance math
//    (__fsub/__fmul/__fadd rn, ((dx^2+dy^2)+dz^2)); ties -> smallest
//    ORIGINAL index everywhere == jnp.argmax.
//    ONE barrier covers both batches; 32-slot reduce: A = slots 0-15,
//    B = slots 16-31, masked REDUX per batch.
// ============================================================================
// dynamic smem layout (bytes):
//   [0,65536)        float2 xyA[8192]  (swizzled)
//   [65536,98304)    float  zA[8192]
//   [98304,163840)   float2 xyB[8192]
//   [163840,196608)  float  zB[8192]
//   [196608,204800)  u32    hist[2048]          (setup scratch)
//   [204800,221184)  u16    orig16[8192]        (setup scratch)
#define FPS_DYN_ 221184

__global__ __launch_bounds__(FT_, 1)
void fps_kernel(const float* __restrict__ coords, float* __restrict__ out_coords)
{
    extern __shared__ unsigned char dyn[];
    float2* xyt[2] = { (float2*)dyn,             (float2*)(dyn + 98304) };
    float*  zzt[2] = { (float*)(dyn + 65536),    (float*)(dyn + 163840) };
    unsigned*       hist = (unsigned*)(dyn + 196608);
    unsigned short* og16 = (unsigned short*)(dyn + 204800);

    __shared__ unsigned s_val[2][32];
    __shared__ unsigned s_idx[2][32];
    __shared__ float4   s_cxyz[2][32];
    __shared__ unsigned s_wsum[16];

    const int t = threadIdx.x;
    const int lane = t & 31;
    const int w    = t >> 5;
    const unsigned FULL = 0xffffffffu;

    const float* cbase[2];
    cbase[0] = coords + (size_t)(2 * blockIdx.x) * (N_ * 3);
    cbase[1] = cbase[0] + N_ * 3;

    float    pd[2 * PPT_];
    unsigned ogp[2 * 8];           // orig indices, 2 x 16-bit per u32
    float    bmn[2][3], bmx[2][3];

    // ---------------- setup: Morton sort per batch ----------------
#pragma unroll
    for (int bt = 0; bt < 2; bt++) {
        for (int v = t; v < NCELL_; v += FT_) hist[v] = 0u;
        __syncthreads();

        float fv[48];
        {
            const float4* src = (const float4*)(cbase[bt] + t * 48);
#pragma unroll
            for (int q = 0; q < 12; q++) {
                float4 v = src[q];
                fv[4*q] = v.x; fv[4*q+1] = v.y; fv[4*q+2] = v.z; fv[4*q+3] = v.w;
            }
        }
#pragma unroll
        for (int j = 0; j < PPT_; j++)
            atomicAdd(&hist[cell_of(fv[3*j], fv[3*j+1], fv[3*j+2])], 1u);
        __syncthreads();

        // exclusive scan of 2048 counters (4 per thread)
        {
            unsigned a0 = hist[t*4], a1 = hist[t*4+1], a2 = hist[t*4+2], a3 = hist[t*4+3];
            unsigned tot = a0 + a1 + a2 + a3;
            unsigned inc = tot;
#pragma unroll
            for (int off = 1; off < 32; off <<= 1) {
                unsigned u = __shfl_up_sync(FULL, inc, off);
                if (lane >= off) inc += u;
            }
            if (lane == 31) s_wsum[w] = inc;
            unsigned exl = inc - tot;
            __syncthreads();
            if (t < 32) {
                unsigned v = (t < 16) ? s_wsum[t] : 0u;
                unsigned i2 = v;
#pragma unroll
                for (int off = 1; off < 32; off <<= 1) {
                    unsigned u = __shfl_up_sync(FULL, i2, off);
                    if (lane >= off) i2 += u;
                }
                if (t < 16) s_wsum[t] = i2 - v;
            }
            __syncthreads();
            unsigned run = s_wsum[w] + exl;
            hist[t*4] = run; run += a0;
            hist[t*4+1] = run; run += a1;
            hist[t*4+2] = run; run += a2;
            hist[t*4+3] = run;
        }
        __syncthreads();

        // scatter
#pragma unroll
        for (int j = 0; j < PPT_; j++) {
            float x = fv[3*j], y = fv[3*j+1], z2 = fv[3*j+2];
            unsigned dst = atomicAdd(&hist[cell_of(x, y, z2)], 1u);
            xyt[bt][sw_xy((int)dst)] = make_float2(x, y);
            zzt[bt][sw_z((int)dst)]  = z2;
            og16[dst] = (unsigned short)(t * PPT_ + j);
        }
        __syncthreads();

        // owner readback: bbox + pd init + orig packing
        {
            float mnx = CUDART_INF_F, mny = CUDART_INF_F, mnz = CUDART_INF_F;
            float mxx = -CUDART_INF_F, mxy = -CUDART_INF_F, mxz = -CUDART_INF_F;
            const int base = t * PPT_;
#pragma unroll
            for (int j = 0; j < PPT_; j++) {
                float2 p = xyt[bt][sw_xy(base + j)];
                float  pz = zzt[bt][sw_z(base + j)];
                mnx = fminf(mnx, p.x); mxx = fmaxf(mxx, p.x);
                mny = fminf(mny, p.y); mxy = fmaxf(mxy, p.y);
                mnz = fminf(mnz, pz);  mxz = fmaxf(mxz, pz);
                pd[bt * PPT_ + j] = 1e10f;
                unsigned og = (unsigned)og16[base + j];
                if ((j & 1) == 0) ogp[bt * 8 + (j >> 1)] = og;
                else              ogp[bt * 8 + (j >> 1)] |= og << 16;
            }
            bmn[bt][0] = mnx; bmn[bt][1] = mny; bmn[bt][2] = mnz;
            bmx[bt][0] = mxx; bmx[bt][1] = mxy; bmx[bt][2] = mxz;
        }
        __syncthreads();   // scratch safe to reuse for next batch
    }

    // ---------------- main loop: both batches interleaved ----------------
    float    m[2]  = { CUDART_INF_F, CUDART_INF_F };   // force 1st compute
    unsigned mi[2] = { 0xffffffffu, 0xffffffffu };
    int      msp[2] = { t * PPT_, t * PPT_ };
    unsigned g[2]  = { 0u, 0u };
    float cx[2], cy[2], cz[2];
#pragma unroll
    for (int bt = 0; bt < 2; bt++) {
        cx[bt] = cbase[bt][0]; cy[bt] = cbase[bt][1]; cz[bt] = cbase[bt][2];
    }

    for (int i = 0; i < S_; i++) {
        if (t == 0) {
#pragma unroll
            for (int bt = 0; bt < 2; bt++) {
                int bb = 2 * blockIdx.x + bt;
                g_fps_idx[bb * S_ + i] = (int)g[bt];
                float* oc = out_coords + ((size_t)bb * S_ + i) * 3;
                oc[0] = cx[bt]; oc[1] = cy[bt]; oc[2] = cz[bt];
            }
        }
        if (i == S_ - 1) break;
        const int buf = i & 1;

#pragma unroll
        for (int bt = 0; bt < 2; bt++) {
            // ---- per-thread bound: skip iff provably a bit-exact no-op ----
            float ax = fmaxf(fmaxf(__fsub_rn(bmn[bt][0], cx[bt]), __fsub_rn(cx[bt], bmx[bt][0])), 0.0f);
            float ay = fmaxf(fmaxf(__fsub_rn(bmn[bt][1], cy[bt]), __fsub_rn(cy[bt], bmx[bt][1])), 0.0f);
            float az = fmaxf(fmaxf(__fsub_rn(bmn[bt][2], cz[bt]), __fsub_rn(cz[bt], bmx[bt][2])), 0.0f);
            float lb = ax * ax + ay * ay + az * az;

            if (!(lb * 0.99999f >= m[bt])) {
                const int base = t * PPT_;
                float nm = -CUDART_INF_F; unsigned nmi = 0xffffffffu; int nj = base;
#pragma unroll
                for (int j = 0; j < PPT_; j++) {
                    float2 p = xyt[bt][sw_xy(base + j)];
                    float  pz = zzt[bt][sw_z(base + j)];
                    float dx = __fsub_rn(p.x, cx[bt]);
                    float dy = __fsub_rn(p.y, cy[bt]);
                    float dz = __fsub_rn(pz,  cz[bt]);
                    float dd = __fadd_rn(__fadd_rn(__fmul_rn(dx, dx), __fmul_rn(dy, dy)),
                                         __fmul_rn(dz, dz));
                    float pdj = fminf(pd[bt * PPT_ + j], dd);
                    pd[bt * PPT_ + j] = pdj;
                    unsigned og = (ogp[bt * 8 + (j >> 1)] >> ((j & 1) * 16)) & 0xFFFFu;
                    if (pdj > nm || (pdj == nm && og < nmi)) { nm = pdj; nmi = og; nj = base + j; }
                }
                m[bt] = nm; mi[bt] = nmi; msp[bt] = nj;
            }

            // ---- warp argmax (pd >= 0: float bits order-isomorphic to u32) ----
            unsigned mb = __float_as_uint(m[bt]);
            unsigned wm = __reduce_max_sync(FULL, mb);
            unsigned cand = (mb == wm) ? mi[bt] : 0xffffffffu;
            unsigned wmi = __reduce_min_sync(FULL, cand);     // min ORIGINAL idx
            if (mb == wm && mi[bt] == wmi) {                  // unique owner lane
                int sl = bt * 16 + w;
                s_val[buf][sl] = wm;
                s_idx[buf][sl] = wmi;
                float2 p = xyt[bt][sw_xy(msp[bt])];
                s_cxyz[buf][sl] = make_float4(p.x, p.y, zzt[bt][sw_z(msp[bt])], 0.0f);
            }
        }
        __syncthreads();

        // ---- every warp reduces both batches' 16 slots (masked REDUX) ----
        unsigned v  = s_val[buf][lane];
        unsigned ix = s_idx[buf][lane];
#pragma unroll
        for (int bt = 0; bt < 2; bt++) {
            bool mine = (bt == 0) ? (lane < 16) : (lane >= 16);
            unsigned vv = mine ? v : 0u;
            unsigned gm = __reduce_max_sync(FULL, vv);
            unsigned c2 = (mine && vv == gm) ? ((ix << 5) | (unsigned)lane) : 0xffffffffu;
            unsigned pk = __reduce_min_sync(FULL, c2);        // min (idx, slot)
            g[bt] = pk >> 5;
            float4 cc = s_cxyz[buf][pk & 31u];
            cx[bt] = cc.x; cy[bt] = cc.y; cz[bt] = cc.z;
        }
    }
}

// ============================================================================
// 2) KNN: K=16 smallest (d, idx) lexicographic (matches top_k(-d)).
// ============================================================================
__global__ __launch_bounds__(128)
void knn_kernel(const float* __restrict__ coords)
{
    const int b = blockIdx.y;
    const int s = blockIdx.x * 128 + threadIdx.x;
    const float* cb = coords + (size_t)b * N_ * 3;

    const int qi = g_fps_idx[b * S_ + s];
    const float qx = cb[qi * 3 + 0];
    const float qy = cb[qi * 3 + 1];
    const float qz = cb[qi * 3 + 2];

    __shared__ float4 tile[2048];     // 32 KB, padded xyz

    float dk[K_];
    int   ik[K_];
#pragma unroll
    for (int j = 0; j < K_; j++) { dk[j] = CUDART_INF_F; ik[j] = 0; }

    for (int t0 = 0; t0 < N_; t0 += 2048) {
        __syncthreads();
        for (int v = threadIdx.x; v < 2048; v += 128) {
            int p = t0 + v;
            tile[v] = make_float4(cb[p * 3 + 0], cb[p * 3 + 1], cb[p * 3 + 2], 0.0f);
        }
        __syncthreads();

#pragma unroll 8
        for (int p = 0; p < 2048; p++) {
            float4 cc = tile[p];
            float dx = __fsub_rn(qx, cc.x);
            float dy = __fsub_rn(qy, cc.y);
            float dz = __fsub_rn(qz, cc.z);
            float dd = __fadd_rn(__fadd_rn(__fmul_rn(dx, dx), __fmul_rn(dy, dy)),
                                 __fmul_rn(dz, dz));
            if (dd < dk[K_ - 1]) {
                float vd = dd; int vi = t0 + p;
#pragma unroll
                for (int j = 0; j < K_; j++) {
                    if (vd < dk[j]) {
                        float td = dk[j]; int ti2 = ik[j];
                        dk[j] = vd; ik[j] = vi;
                        vd = td; vi = ti2;
                    }
                }
            }
        }
    }

    int* out = &g_knn_idx[((size_t)b * S_ + s) * K_];
#pragma unroll
    for (int j = 0; j < K_; j++) out[j] = ik[j];
}

// ============================================================================
// 3) Pointwise MLP (64->128) + BN(eval) + ReLU -> g_h (3 launches before fps
//    keeps fps on the ncu -s 5 -c 1 capture slot).
// ============================================================================
__global__ __launch_bounds__(256)
void mlp_kernel(const float* __restrict__ features,
                const float* __restrict__ W,
                const float* __restrict__ bias,
                const float* __restrict__ gamma,
                const float* __restrict__ beta,
                const float* __restrict__ rmean,
                const float* __restrict__ rvar,
                int blk0)
{
    const int pt0  = (blk0 + blockIdx.x) * 32;
    const int o    = threadIdx.x & 127;
    const int half = threadIdx.x >> 7;

    __shared__ float sW[DOUT_ * DIN_];          // 32 KB
    __shared__ float sF[32 * DIN_];             // 8 KB

    for (int v = threadIdx.x; v < DOUT_ * DIN_; v += 256) sW[v] = W[v];
    for (int v = threadIdx.x; v < 32 * DIN_;   v += 256) sF[v] = features[(size_t)pt0 * DIN_ + v];
    __syncthreads();

    float w[DIN_];
#pragma unroll
    for (int d = 0; d < DIN_; d++) w[d] = sW[o * DIN_ + d];

    const float bo = bias[o];
    const float mn = rmean[o];
    const float sc = gamma[o] * rsqrtf(rvar[o] + BN_EPS_);
    const float bt = beta[o];

    for (int p = half * 16; p < half * 16 + 16; p++) {
        float acc = 0.0f;
#pragma unroll
        for (int d = 0; d < DIN_; d += 4) {
            float4 ff = *(const float4*)&sF[p * DIN_ + d];
            acc = fmaf(w[d + 0], ff.x, acc);
            acc = fmaf(w[d + 1], ff.y, acc);
            acc = fmaf(w[d + 2], ff.z, acc);
            acc = fmaf(w[d + 3], ff.w, acc);
        }
        float lin = acc + bo;
        float val = (lin - mn) * sc + bt;
        g_h[((size_t)pt0 + p) * DOUT_ + o] = fmaxf(val, 0.0f);
    }
}

// ============================================================================
// 4) Gather K neighbors' features + max-pool (two launches).
// ============================================================================
__global__ __launch_bounds__(256)
void pool_kernel(float* __restrict__ out_feat, int b0)
{
    const int b   = b0 + blockIdx.y;
    const int s   = blockIdx.x * 8 + (threadIdx.x >> 5);
    const int col = threadIdx.x & 31;

    const int* kid = &g_knn_idx[((size_t)b * S_ + s) * K_];

    float4 acc = make_float4(-CUDART_INF_F, -CUDART_INF_F, -CUDART_INF_F, -CUDART_INF_F);
#pragma unroll
    for (int k = 0; k < K_; k++) {
        const int id = kid[k];
        const float4 v = *(const float4*)&g_h[((size_t)b * N_ + id) * DOUT_ + col * 4];
        acc.x = fmaxf(acc.x, v.x);
        acc.y = fmaxf(acc.y, v.y);
        acc.z = fmaxf(acc.z, v.z);
        acc.w = fmaxf(acc.w, v.w);
    }
    *(float4*)&out_feat[((size_t)b * S_ + s) * DOUT_ + col * 4] = acc;
}

// ============================================================================
extern "C" void kernel_launch(void* const* d_in, const int* in_sizes, int n_in,
                              void* d_out, int out_size)
{
    const float* coords   = (const float*)d_in[0];
    const float* features = (const float*)d_in[1];
    const float* W        = (const float*)d_in[2];
    const float* bias     = (const float*)d_in[3];
    const float* gamma    = (const float*)d_in[4];
    const float* beta     = (const float*)d_in[5];
    const float* rmean    = (const float*)d_in[6];
    const float* rvar     = (const float*)d_in[7];

    float* out        = (float*)d_out;
    float* out_coords = out;                       // [B, S, 3]
    float* out_feat   = out + (size_t)B_ * S_ * 3; // [B, S, 128]

    static bool attr_done = false;
    if (!attr_done) {
        cudaFuncSetAttribute(fps_kernel, cudaFuncAttributeMaxDynamicSharedMemorySize,
                             FPS_DYN_);
        attr_done = true;
    }

    // mlp split x3 before fps keeps fps_kernel on the ncu capture slot.
    mlp_kernel<<<683, 256>>>(features, W, bias, gamma, beta, rmean, rvar, 0);
    mlp_kernel<<<683, 256>>>(features, W, bias, gamma, beta, rmean, rvar, 683);
    mlp_kernel<<<682, 256>>>(features, W, bias, gamma, beta, rmean, rvar, 1366);
    fps_kernel<<<B_ / 2, FT_, FPS_DYN_>>>(coords, out_coords);
    knn_kernel<<<dim3(S_ / 128, B_), 128>>>(coords);
    pool_kernel<<<dim3(S_ / 8, 4), 256>>>(out_feat, 0);
    pool_kernel<<<dim3(S_ / 8, 4), 256>>>(out_feat, 4);
}

// round 16
// speedup vs baseline: 1.9383x; 1.9383x over previous
#include <cuda_runtime.h>
#include <cuda_bf16.h>
#include <math_constants.h>

#define B_      8
#define N_      8192
#define S_      2048
#define K_      16
#define DIN_    64
#define DOUT_   128
#define BN_EPS_ 1e-5f

#define FT_     512            // FPS threads (16 warps)
#define PPT_    16             // points per thread (Morton-contiguous)
#define NCELL_  4096           // 16x16x16 spatial cells, Morton-ordered

// ---------------- scratch (static __device__ — no allocation allowed) ----------------
__device__ int   g_fps_idx[B_ * S_];
__device__ int   g_knn_idx[B_ * S_ * K_];
__device__ float g_h[B_ * N_ * DOUT_];   // 33.5 MB, post MLP+BN+ReLU features

// ---------------- packed f32x2 helpers (exact IEEE per lane) ----------------
__device__ __forceinline__ unsigned long long pack2(float lo, float hi) {
    unsigned long long r;
    asm("mov.b64 %0, {%1, %2};" : "=l"(r) : "f"(lo), "f"(hi));
    return r;
}
__device__ __forceinline__ void unpack2(unsigned long long v, float& lo, float& hi) {
    asm("mov.b64 {%0, %1}, %2;" : "=f"(lo), "=f"(hi) : "l"(v));
}
__device__ __forceinline__ unsigned long long add2(unsigned long long a, unsigned long long b) {
    unsigned long long r;
    asm("add.rn.f32x2 %0, %1, %2;" : "=l"(r) : "l"(a), "l"(b));
    return r;
}
__device__ __forceinline__ unsigned long long mul2(unsigned long long a, unsigned long long b) {
    unsigned long long r;
    asm("mul.rn.f32x2 %0, %1, %2;" : "=l"(r) : "l"(a), "l"(b));
    return r;
}
// 4-bit Morton spread: bits -> positions 0,3,6,9 (setup only)
__device__ __forceinline__ unsigned spread3(unsigned v) {
    return (v & 1u) | ((v & 2u) << 2) | ((v & 4u) << 4) | ((v & 8u) << 6);
}

// ============================================================================
// 1) FPS — round-12 structure (best: 1628 us) with the post-barrier slot
//    reduce replaced by a COLLECTIVE-FREE broadcast tree:
//      owner lane packs u64 key = (val<<18) | ((8191-idx)<<5) | warp, writes
//      key (STS.64) + coords (STS.128); after the single barrier every
//      thread reads the 16 warp keys (broadcast LDS.64, conflict-free) and
//      max-trees them in registers. u64 max == (max val, tie -> min ORIGINAL
//      idx) exactly == jnp.argmax; slot bits never decide (idx unique).
//    Everything else identical: Morton sort, per-thread bound check,
//    NEGATED packed-f32x2 register math ((-p)+c == -(p-c) bit-exactly),
//    warp REDUX pair, double-buffered slots.
// ============================================================================
extern __shared__ float4 s_sort[];   // [N_] Morton-sorted coords, orig idx in .w

__global__ __launch_bounds__(FT_, 1)
void fps_kernel(const float* __restrict__ coords, float* __restrict__ out_coords)
{
    __shared__ unsigned s_hist[NCELL_];          // 16 KB
    __shared__ unsigned s_wsum[32];
    __shared__ unsigned long long s_key[2][16];
    __shared__ float4   s_cxyz[2][16];

    const int b    = blockIdx.x;
    const int t    = threadIdx.x;
    const int lane = t & 31;
    const int w    = t >> 5;
    const unsigned FULL = 0xffffffffu;
    const float* cb = coords + (size_t)b * N_ * 3;

    // ---------------- setup: Morton counting sort ----------------
    for (int v = t; v < NCELL_; v += FT_) s_hist[v] = 0u;
    __syncthreads();

    float fv[48];
    unsigned cells[PPT_];
    {
        const float4* src = (const float4*)(cb + t * 48);   // points 16t..16t+15
#pragma unroll
        for (int q = 0; q < 12; q++) {
            float4 v = src[q];
            fv[q * 4 + 0] = v.x; fv[q * 4 + 1] = v.y; fv[q * 4 + 2] = v.z; fv[q * 4 + 3] = v.w;
        }
#pragma unroll
        for (int j = 0; j < PPT_; j++) {
            unsigned bx = (unsigned)min(max((int)floorf(fv[3 * j + 0] * 2.0f) + 8, 0), 15);
            unsigned by = (unsigned)min(max((int)floorf(fv[3 * j + 1] * 2.0f) + 8, 0), 15);
            unsigned bz = (unsigned)min(max((int)floorf(fv[3 * j + 2] * 2.0f) + 8, 0), 15);
            cells[j] = spread3(bx) | (spread3(by) << 1) | (spread3(bz) << 2);
            atomicAdd(&s_hist[cells[j]], 1u);
        }
    }
    __syncthreads();
    // parallel exclusive scan of 4096 counters (each thread owns 8)
    {
        unsigned a[8];
#pragma unroll
        for (int k = 0; k < 8; k++) a[k] = s_hist[t * 8 + k];
        unsigned tot = 0;
#pragma unroll
        for (int k = 0; k < 8; k++) tot += a[k];
        unsigned inc = tot;
#pragma unroll
        for (int off = 1; off < 32; off <<= 1) {
            unsigned u = __shfl_up_sync(FULL, inc, off);
            if (lane >= off) inc += u;
        }
        if (lane == 31) s_wsum[w] = inc;
        unsigned exl = inc - tot;
        __syncthreads();
        if (t < 32) {
            unsigned v = (t < 16) ? s_wsum[t] : 0u;
            unsigned i2 = v;
#pragma unroll
            for (int off = 1; off < 32; off <<= 1) {
                unsigned u = __shfl_up_sync(FULL, i2, off);
                if (lane >= off) i2 += u;
            }
            if (t < 16) s_wsum[t] = i2 - v;
        }
        __syncthreads();
        unsigned run = s_wsum[w] + exl;
#pragma unroll
        for (int k = 0; k < 8; k++) { s_hist[t * 8 + k] = run; run += a[k]; }
    }
    __syncthreads();
#pragma unroll
    for (int j = 0; j < PPT_; j++) {
        unsigned dst = atomicAdd(&s_hist[cells[j]], 1u);
        unsigned orig = (unsigned)(t * PPT_ + j);
        s_sort[dst] = make_float4(fv[3 * j], fv[3 * j + 1], fv[3 * j + 2],
                                  __uint_as_float(orig));
    }
    __syncthreads();

    // ---- pull my 16 Morton-sorted points into registers + bbox ----
    unsigned long long npx[8], npy[8], npz[8];
    unsigned ogr[PPT_];
    float pd[PPT_];
    float bmnx = CUDART_INF_F, bmny = CUDART_INF_F, bmnz = CUDART_INF_F;
    float bmxx = -CUDART_INF_F, bmxy = -CUDART_INF_F, bmxz = -CUDART_INF_F;
    {
        const int base = t * PPT_;
        float sx[PPT_], sy[PPT_], sz[PPT_];
#pragma unroll
        for (int j = 0; j < PPT_; j++) {
            float4 p4 = s_sort[base + j];
            sx[j] = p4.x; sy[j] = p4.y; sz[j] = p4.z;
            bmnx = fminf(bmnx, p4.x); bmxx = fmaxf(bmxx, p4.x);
            bmny = fminf(bmny, p4.y); bmxy = fmaxf(bmxy, p4.y);
            bmnz = fminf(bmnz, p4.z); bmxz = fmaxf(bmxz, p4.z);
            pd[j] = 1e10f;
            ogr[j] = __float_as_uint(p4.w);
        }
#pragma unroll
        for (int jj = 0; jj < 8; jj++) {
            npx[jj] = pack2(-sx[2 * jj], -sx[2 * jj + 1]);
            npy[jj] = pack2(-sy[2 * jj], -sy[2 * jj + 1]);
            npz[jj] = pack2(-sz[2 * jj], -sz[2 * jj + 1]);
        }
    }

    float    m   = CUDART_INF_F;       // cached max_j pd[j] (forces 1st compute)
    unsigned mi  = 0xffffffffu;        // cached argmax original index
    int      msp = t * PPT_;           // cached argmax sorted slot

    unsigned g = 0u;
    float4 c = make_float4(cb[0], cb[1], cb[2], 0.0f);   // start at point 0

    for (int i = 0; i < S_; i++) {
        if (t == 0) {
            g_fps_idx[b * S_ + i] = (int)g;
            float* oc = out_coords + ((size_t)b * S_ + i) * 3;
            oc[0] = c.x; oc[1] = c.y; oc[2] = c.z;
        }
        if (i == S_ - 1) break;
        const int buf = i & 1;

        // ---- per-thread bound: skip iff provably a bit-exact no-op ----
        float ax = fmaxf(fmaxf(__fsub_rn(bmnx, c.x), __fsub_rn(c.x, bmxx)), 0.0f);
        float ay = fmaxf(fmaxf(__fsub_rn(bmny, c.y), __fsub_rn(c.y, bmxy)), 0.0f);
        float az = fmaxf(fmaxf(__fsub_rn(bmnz, c.z), __fsub_rn(c.z, bmxz)), 0.0f);
        float lb = ax * ax + ay * ay + az * az;

        if (!(lb * 0.99999f >= m)) {
            // packed recompute: exact IEEE (-p)+c, mul, ((x+y)+z)
            const unsigned long long cxx = pack2(c.x, c.x);
            const unsigned long long cyy = pack2(c.y, c.y);
            const unsigned long long czz = pack2(c.z, c.z);
#pragma unroll
            for (int jj = 0; jj < 8; jj++) {
                unsigned long long dx = add2(npx[jj], cxx);
                unsigned long long dy = add2(npy[jj], cyy);
                unsigned long long dz = add2(npz[jj], czz);
                unsigned long long dd = add2(add2(mul2(dx, dx), mul2(dy, dy)), mul2(dz, dz));
                float d0, d1;
                unpack2(dd, d0, d1);
                pd[2 * jj]     = fminf(pd[2 * jj],     d0);
                pd[2 * jj + 1] = fminf(pd[2 * jj + 1], d1);
            }
            // exact argmax: value tree, then min-orig among equal maxima
            float vm = pd[0];
#pragma unroll
            for (int j = 1; j < PPT_; j++) vm = fmaxf(vm, pd[j]);
            unsigned nmi = 0xffffffffu; int nj = 0;
#pragma unroll
            for (int j = 0; j < PPT_; j++)
                if (pd[j] == vm && ogr[j] < nmi) { nmi = ogr[j]; nj = j; }
            m = vm; mi = nmi; msp = t * PPT_ + nj;
        }

        // ---- warp argmax (pd >= 0: float bits order-isomorphic to u32) ----
        unsigned mb = __float_as_uint(m);
        unsigned wm = __reduce_max_sync(FULL, mb);
        unsigned cand = (mb == wm) ? mi : 0xffffffffu;
        unsigned wmi = __reduce_min_sync(FULL, cand);     // min ORIGINAL index
        if (mb == wm && mi == wmi) {                      // unique owner lane
            s_key[buf][w] = ((unsigned long long)wm << 18) |
                            ((unsigned long long)(8191u - wmi) << 5) |
                            (unsigned long long)w;
            s_cxyz[buf][w] = s_sort[msp];                 // owner-only LDS.128
        }
        __syncthreads();

        // ---- collective-free final reduce: broadcast LDS.64 + reg max tree ----
        unsigned long long k0, k1;
        {
            unsigned long long ka = s_key[buf][0],  kb2 = s_key[buf][1];
            unsigned long long kc = s_key[buf][2],  kd = s_key[buf][3];
            unsigned long long ke = s_key[buf][4],  kf = s_key[buf][5];
            unsigned long long kg2 = s_key[buf][6], kh = s_key[buf][7];
            unsigned long long ki = s_key[buf][8],  kj = s_key[buf][9];
            unsigned long long kk2 = s_key[buf][10], kl = s_key[buf][11];
            unsigned long long km = s_key[buf][12], kn = s_key[buf][13];
            unsigned long long ko = s_key[buf][14], kp = s_key[buf][15];
            ka = (kb2 > ka) ? kb2 : ka;  kc = (kd > kc) ? kd : kc;
            ke = (kf > ke) ? kf : ke;    kg2 = (kh > kg2) ? kh : kg2;
            ki = (kj > ki) ? kj : ki;    kk2 = (kl > kk2) ? kl : kk2;
            km = (kn > km) ? kn : km;    ko = (kp > ko) ? kp : ko;
            ka = (kc > ka) ? kc : ka;    ke = (kg2 > ke) ? kg2 : ke;
            ki = (kk2 > ki) ? kk2 : ki;  km = (ko > km) ? ko : km;
            k0 = (ke > ka) ? ke : ka;    k1 = (km > ki) ? km : ki;
        }
        unsigned long long kw = (k1 > k0) ? k1 : k0;
        g = 8191u - (unsigned)((kw >> 5) & 0x1FFFu);
        c = s_cxyz[buf][(int)(kw & 31u)];                 // broadcast LDS.128
    }
}

// ============================================================================
// 2) KNN: K=16 smallest (d, idx) lexicographic (matches top_k(-d)).
// ============================================================================
__global__ __launch_bounds__(128)
void knn_kernel(const float* __restrict__ coords)
{
    const int b = blockIdx.y;
    const int s = blockIdx.x * 128 + threadIdx.x;
    const float* cb = coords + (size_t)b * N_ * 3;

    const int qi = g_fps_idx[b * S_ + s];
    const float qx = cb[qi * 3 + 0];
    const float qy = cb[qi * 3 + 1];
    const float qz = cb[qi * 3 + 2];

    __shared__ float4 tile[2048];     // 32 KB, padded xyz

    float dk[K_];
    int   ik[K_];
#pragma unroll
    for (int j = 0; j < K_; j++) { dk[j] = CUDART_INF_F; ik[j] = 0; }

    for (int t0 = 0; t0 < N_; t0 += 2048) {
        __syncthreads();
        for (int v = threadIdx.x; v < 2048; v += 128) {
            int p = t0 + v;
            tile[v] = make_float4(cb[p * 3 + 0], cb[p * 3 + 1], cb[p * 3 + 2], 0.0f);
        }
        __syncthreads();

#pragma unroll 8
        for (int p = 0; p < 2048; p++) {
            float4 cc = tile[p];
            float dx = __fsub_rn(qx, cc.x);
            float dy = __fsub_rn(qy, cc.y);
            float dz = __fsub_rn(qz, cc.z);
            float dd = __fadd_rn(__fadd_rn(__fmul_rn(dx, dx), __fmul_rn(dy, dy)),
                                 __fmul_rn(dz, dz));
            if (dd < dk[K_ - 1]) {
                float vd = dd; int vi = t0 + p;
#pragma unroll
                for (int j = 0; j < K_; j++) {
                    if (vd < dk[j]) {
                        float td = dk[j]; int ti2 = ik[j];
                        dk[j] = vd; ik[j] = vi;
                        vd = td; vi = ti2;
                    }
                }
            }
        }
    }

    int* out = &g_knn_idx[((size_t)b * S_ + s) * K_];
#pragma unroll
    for (int j = 0; j < K_; j++) out[j] = ik[j];
}

// ============================================================================
// 3) Pointwise MLP (64->128) + BN(eval) + ReLU -> g_h (3 launches before fps
//    keeps fps on the ncu -s 5 -c 1 capture slot).
// ============================================================================
__global__ __launch_bounds__(256)
void mlp_kernel(const float* __restrict__ features,
                const float* __restrict__ W,
                const float* __restrict__ bias,
                const float* __restrict__ gamma,
                const float* __restrict__ beta,
                const float* __restrict__ rmean,
                const float* __restrict__ rvar,
                int blk0)
{
    const int pt0  = (blk0 + blockIdx.x) * 32;
    const int o    = threadIdx.x & 127;
    const int half = threadIdx.x >> 7;

    __shared__ float sW[DOUT_ * DIN_];          // 32 KB
    __shared__ float sF[32 * DIN_];             // 8 KB

    for (int v = threadIdx.x; v < DOUT_ * DIN_; v += 256) sW[v] = W[v];
    for (int v = threadIdx.x; v < 32 * DIN_;   v += 256) sF[v] = features[(size_t)pt0 * DIN_ + v];
    __syncthreads();

    float w[DIN_];
#pragma unroll
    for (int d = 0; d < DIN_; d++) w[d] = sW[o * DIN_ + d];

    const float bo = bias[o];
    const float mn = rmean[o];
    const float sc = gamma[o] * rsqrtf(rvar[o] + BN_EPS_);
    const float bt = beta[o];

    for (int p = half * 16; p < half * 16 + 16; p++) {
        float acc = 0.0f;
#pragma unroll
        for (int d = 0; d < DIN_; d += 4) {
            float4 ff = *(const float4*)&sF[p * DIN_ + d];
            acc = fmaf(w[d + 0], ff.x, acc);
            acc = fmaf(w[d + 1], ff.y, acc);
            acc = fmaf(w[d + 2], ff.z, acc);
            acc = fmaf(w[d + 3], ff.w, acc);
        }
        float lin = acc + bo;
        float val = (lin - mn) * sc + bt;
        g_h[((size_t)pt0 + p) * DOUT_ + o] = fmaxf(val, 0.0f);
    }
}

// ============================================================================
// 4) Gather K neighbors' features + max-pool (two launches).
// ============================================================================
__global__ __launch_bounds__(256)
void pool_kernel(float* __restrict__ out_feat, int b0)
{
    const int b   = b0 + blockIdx.y;
    const int s   = blockIdx.x * 8 + (threadIdx.x >> 5);
    const int col = threadIdx.x & 31;

    const int* kid = &g_knn_idx[((size_t)b * S_ + s) * K_];

    float4 acc = make_float4(-CUDART_INF_F, -CUDART_INF_F, -CUDART_INF_F, -CUDART_INF_F);
#pragma unroll
    for (int k = 0; k < K_; k++) {
        const int id = kid[k];
        const float4 v = *(const float4*)&g_h[((size_t)b * N_ + id) * DOUT_ + col * 4];
        acc.x = fmaxf(acc.x, v.x);
        acc.y = fmaxf(acc.y, v.y);
        acc.z = fmaxf(acc.z, v.z);
        acc.w = fmaxf(acc.w, v.w);
    }
    *(float4*)&out_feat[((size_t)b * S_ + s) * DOUT_ + col * 4] = acc;
}

// ============================================================================
extern "C" void kernel_launch(void* const* d_in, const int* in_sizes, int n_in,
                              void* d_out, int out_size)
{
    const float* coords   = (const float*)d_in[0];
    const float* features = (const float*)d_in[1];
    const float* W        = (const float*)d_in[2];
    const float* bias     = (const float*)d_in[3];
    const float* gamma    = (const float*)d_in[4];
    const float* beta     = (const float*)d_in[5];
    const float* rmean    = (const float*)d_in[6];
    const float* rvar     = (const float*)d_in[7];

    float* out        = (float*)d_out;
    float* out_coords = out;                       // [B, S, 3]
    float* out_feat   = out + (size_t)B_ * S_ * 3; // [B, S, 128]

    const int fps_dyn_bytes = N_ * (int)sizeof(float4);
    static bool attr_done = false;
    if (!attr_done) {
        cudaFuncSetAttribute(fps_kernel, cudaFuncAttributeMaxDynamicSharedMemorySize,
                             fps_dyn_bytes);
        attr_done = true;
    }

    // mlp split x3 before fps keeps fps_kernel on the ncu capture slot.
    mlp_kernel<<<683, 256>>>(features, W, bias, gamma, beta, rmean, rvar, 0);
    mlp_kernel<<<683, 256>>>(features, W, bias, gamma, beta, rmean, rvar, 683);
    mlp_kernel<<<682, 256>>>(features, W, bias, gamma, beta, rmean, rvar, 1366);
    fps_kernel<<<B_, FT_, fps_dyn_bytes>>>(coords, out_coords);
    knn_kernel<<<dim3(S_ / 128, B_), 128>>>(coords);
    pool_kernel<<<dim3(S_ / 8, 4), 256>>>(out_feat, 0);
    pool_kernel<<<dim3(S_ / 8, 4), 256>>>(out_feat, 4);
}

// round 17
// speedup vs baseline: 2.2505x; 1.1611x over previous
#include <cuda_runtime.h>
#include <cuda_bf16.h>
#include <math_constants.h>

#define B_      8
#define N_      8192
#define S_      2048
#define K_      16
#define DIN_    64
#define DOUT_   128
#define BN_EPS_ 1e-5f

#define FT_     512            // FPS threads (16 warps)
#define PPT_    16             // points per thread (Morton-contiguous)
#define NCELL_  4096           // 16x16x16 spatial cells, Morton-ordered

// ---------------- scratch (static __device__ — no allocation allowed) ----------------
__device__ int   g_fps_idx[B_ * S_];
__device__ int   g_knn_idx[B_ * S_ * K_];
__device__ float g_h[B_ * N_ * DOUT_];   // 33.5 MB, post MLP+BN+ReLU features

// ---------------- packed f32x2 helpers (exact IEEE per lane) ----------------
__device__ __forceinline__ unsigned long long pack2(float lo, float hi) {
    unsigned long long r;
    asm("mov.b64 %0, {%1, %2};" : "=l"(r) : "f"(lo), "f"(hi));
    return r;
}
__device__ __forceinline__ void unpack2(unsigned long long v, float& lo, float& hi) {
    asm("mov.b64 {%0, %1}, %2;" : "=f"(lo), "=f"(hi) : "l"(v));
}
__device__ __forceinline__ unsigned long long add2(unsigned long long a, unsigned long long b) {
    unsigned long long r;
    asm("add.rn.f32x2 %0, %1, %2;" : "=l"(r) : "l"(a), "l"(b));
    return r;
}
__device__ __forceinline__ unsigned long long mul2(unsigned long long a, unsigned long long b) {
    unsigned long long r;
    asm("mul.rn.f32x2 %0, %1, %2;" : "=l"(r) : "l"(a), "l"(b));
    return r;
}
// 4-bit Morton spread: bits -> positions 0,3,6,9 (setup only)
__device__ __forceinline__ unsigned spread3(unsigned v) {
    return (v & 1u) | ((v & 2u) << 2) | ((v & 4u) << 4) | ((v & 8u) << 6);
}

// ============================================================================
// 1) FPS — round-12 base (best) + WARP-UNIFORM exact pruning:
//    a warp's 512 Morton-contiguous points get a butterfly-reduced warp bbox
//    (register-replicated). Per iteration the warp-uniform check
//    lb(c,warp_bbox)*0.99999 >= cached warp max-pd proves EVERY lane's
//    fminf(pd, d) is a bit-exact no-op -> the whole warp skips compute and
//    both REDUXes (cached warp winner re-emitted by lane 0). Computing warps
//    run R12's conflict-free NEGATED packed-f32x2 register math
//    ((-p)+c == -(p-c) bit-exactly; squaring erases the sign) with exact
//    IEEE ordering and ORIGINAL-index tie-breaks (== jnp.argmax).
//    One barrier/iter; double-buffered 32-slot reduce (16 real + 16 dummy).
// ============================================================================
extern __shared__ float4 s_sort[];   // [N_] Morton-sorted coords, orig idx in .w

__global__ __launch_bounds__(FT_, 1)
void fps_kernel(const float* __restrict__ coords, float* __restrict__ out_coords)
{
    __shared__ unsigned s_hist[NCELL_];          // 16 KB
    __shared__ unsigned s_wsum[32];
    __shared__ unsigned s_val[2][32];
    __shared__ unsigned s_idx[2][32];
    __shared__ float4   s_cxyz[2][32];

    const int b    = blockIdx.x;
    const int t    = threadIdx.x;
    const int lane = t & 31;
    const int w    = t >> 5;
    const unsigned FULL = 0xffffffffu;
    const float* cb = coords + (size_t)b * N_ * 3;

    // ---------------- setup: Morton counting sort ----------------
    for (int v = t; v < NCELL_; v += FT_) s_hist[v] = 0u;
    if (t >= 16 && t < 32) {
        s_val[0][t] = 0u;        s_val[1][t] = 0u;
        s_idx[0][t] = 0xFFFFFFu; s_idx[1][t] = 0xFFFFFFu;   // (idx<<5) safe
    }
    __syncthreads();

    float fv[48];
    unsigned cells[PPT_];
    {
        const float4* src = (const float4*)(cb + t * 48);   // points 16t..16t+15
#pragma unroll
        for (int q = 0; q < 12; q++) {
            float4 v = src[q];
            fv[q * 4 + 0] = v.x; fv[q * 4 + 1] = v.y; fv[q * 4 + 2] = v.z; fv[q * 4 + 3] = v.w;
        }
#pragma unroll
        for (int j = 0; j < PPT_; j++) {
            unsigned bx = (unsigned)min(max((int)floorf(fv[3 * j + 0] * 2.0f) + 8, 0), 15);
            unsigned by = (unsigned)min(max((int)floorf(fv[3 * j + 1] * 2.0f) + 8, 0), 15);
            unsigned bz = (unsigned)min(max((int)floorf(fv[3 * j + 2] * 2.0f) + 8, 0), 15);
            cells[j] = spread3(bx) | (spread3(by) << 1) | (spread3(bz) << 2);
            atomicAdd(&s_hist[cells[j]], 1u);
        }
    }
    __syncthreads();
    // parallel exclusive scan of 4096 counters (each thread owns 8)
    {
        unsigned a[8];
#pragma unroll
        for (int k = 0; k < 8; k++) a[k] = s_hist[t * 8 + k];
        unsigned tot = 0;
#pragma unroll
        for (int k = 0; k < 8; k++) tot += a[k];
        unsigned inc = tot;
#pragma unroll
        for (int off = 1; off < 32; off <<= 1) {
            unsigned u = __shfl_up_sync(FULL, inc, off);
            if (lane >= off) inc += u;
        }
        if (lane == 31) s_wsum[w] = inc;
        unsigned exl = inc - tot;
        __syncthreads();
        if (t < 32) {
            unsigned v = (t < 16) ? s_wsum[t] : 0u;
            unsigned i2 = v;
#pragma unroll
            for (int off = 1; off < 32; off <<= 1) {
                unsigned u = __shfl_up_sync(FULL, i2, off);
                if (lane >= off) i2 += u;
            }
            if (t < 16) s_wsum[t] = i2 - v;
        }
        __syncthreads();
        unsigned run = s_wsum[w] + exl;
#pragma unroll
        for (int k = 0; k < 8; k++) { s_hist[t * 8 + k] = run; run += a[k]; }
    }
    __syncthreads();
#pragma unroll
    for (int j = 0; j < PPT_; j++) {
        unsigned dst = atomicAdd(&s_hist[cells[j]], 1u);
        unsigned orig = (unsigned)(t * PPT_ + j);
        s_sort[dst] = make_float4(fv[3 * j], fv[3 * j + 1], fv[3 * j + 2],
                                  __uint_as_float(orig));
    }
    __syncthreads();

    // ---- pull my 16 Morton-sorted points into registers + WARP bbox ----
    unsigned long long npx[8], npy[8], npz[8];
    unsigned ogp[8];                   // orig indices, 2 x 16-bit per u32
    float pd[PPT_];
    float bmnx = CUDART_INF_F, bmny = CUDART_INF_F, bmnz = CUDART_INF_F;
    float bmxx = -CUDART_INF_F, bmxy = -CUDART_INF_F, bmxz = -CUDART_INF_F;
    {
        const int base = t * PPT_;
        float sx[PPT_], sy[PPT_], sz[PPT_];
#pragma unroll
        for (int j = 0; j < PPT_; j++) {
            float4 p4 = s_sort[base + j];
            sx[j] = p4.x; sy[j] = p4.y; sz[j] = p4.z;
            bmnx = fminf(bmnx, p4.x); bmxx = fmaxf(bmxx, p4.x);
            bmny = fminf(bmny, p4.y); bmxy = fmaxf(bmxy, p4.y);
            bmnz = fminf(bmnz, p4.z); bmxz = fmaxf(bmxz, p4.z);
            pd[j] = 1e10f;
            unsigned og = __float_as_uint(p4.w);
            if ((j & 1) == 0) ogp[j >> 1] = og;
            else              ogp[j >> 1] |= og << 16;
        }
#pragma unroll
        for (int jj = 0; jj < 8; jj++) {
            npx[jj] = pack2(-sx[2 * jj], -sx[2 * jj + 1]);
            npy[jj] = pack2(-sy[2 * jj], -sy[2 * jj + 1]);
            npz[jj] = pack2(-sz[2 * jj], -sz[2 * jj + 1]);
        }
        // butterfly -> warp bbox, replicated in the same registers
#pragma unroll
        for (int off = 16; off > 0; off >>= 1) {
            bmnx = fminf(bmnx, __shfl_xor_sync(FULL, bmnx, off));
            bmny = fminf(bmny, __shfl_xor_sync(FULL, bmny, off));
            bmnz = fminf(bmnz, __shfl_xor_sync(FULL, bmnz, off));
            bmxx = fmaxf(bmxx, __shfl_xor_sync(FULL, bmxx, off));
            bmxy = fmaxf(bmxy, __shfl_xor_sync(FULL, bmxy, off));
            bmxz = fmaxf(bmxz, __shfl_xor_sync(FULL, bmxz, off));
        }
    }

    // cached warp winner (register-replicated; inf forces first compute)
    float    m_w   = CUDART_INF_F;
    unsigned wm_c  = 0x7F800000u;
    unsigned wmi_c = 0xffffffffu;
    float    cwx = 0.f, cwy = 0.f, cwz = 0.f;

    unsigned g = 0u;
    float4 c = make_float4(cb[0], cb[1], cb[2], 0.0f);   // start at point 0

    for (int i = 0; i < S_; i++) {
        if (t == 0) {
            g_fps_idx[b * S_ + i] = (int)g;
            float* oc = out_coords + ((size_t)b * S_ + i) * 3;
            oc[0] = c.x; oc[1] = c.y; oc[2] = c.z;
        }
        if (i == S_ - 1) break;
        const int buf = i & 1;

        // ---- WARP-UNIFORM bound: skip iff provably a bit-exact no-op ----
        float ax = fmaxf(fmaxf(__fsub_rn(bmnx, c.x), __fsub_rn(c.x, bmxx)), 0.0f);
        float ay = fmaxf(fmaxf(__fsub_rn(bmny, c.y), __fsub_rn(c.y, bmxy)), 0.0f);
        float az = fmaxf(fmaxf(__fsub_rn(bmnz, c.z), __fsub_rn(c.z, bmxz)), 0.0f);
        float lb = ax * ax + ay * ay + az * az;

        if (!(lb * 0.99999f >= m_w)) {
            // packed recompute: exact IEEE (-p)+c, mul, ((x+y)+z)
            const unsigned long long cxx = pack2(c.x, c.x);
            const unsigned long long cyy = pack2(c.y, c.y);
            const unsigned long long czz = pack2(c.z, c.z);
#pragma unroll
            for (int jj = 0; jj < 8; jj++) {
                unsigned long long dx = add2(npx[jj], cxx);
                unsigned long long dy = add2(npy[jj], cyy);
                unsigned long long dz = add2(npz[jj], czz);
                unsigned long long dd = add2(add2(mul2(dx, dx), mul2(dy, dy)), mul2(dz, dz));
                float d0, d1;
                unpack2(dd, d0, d1);
                pd[2 * jj]     = fminf(pd[2 * jj],     d0);
                pd[2 * jj + 1] = fminf(pd[2 * jj + 1], d1);
            }
            // exact thread argmax: value tree, then min-orig among maxima
            float vm = pd[0];
#pragma unroll
            for (int j = 1; j < PPT_; j++) vm = fmaxf(vm, pd[j]);
            unsigned nmi = 0xffffffffu; int nj = 0;
#pragma unroll
            for (int j = 0; j < PPT_; j++) {
                unsigned og = (ogp[j >> 1] >> ((j & 1) * 16)) & 0xFFFFu;
                if (pd[j] == vm && og < nmi) { nmi = og; nj = j; }
            }
            // warp argmax (pd >= 0: float bits order-isomorphic to u32)
            unsigned mb = __float_as_uint(vm);
            unsigned wm = __reduce_max_sync(FULL, mb);
            unsigned cand = (mb == wm) ? nmi : 0xffffffffu;
            unsigned wmi = __reduce_min_sync(FULL, cand);     // min ORIGINAL idx
            // owner broadcasts winner coords (unique: orig idx unique)
            unsigned obal = __ballot_sync(FULL, (mb == wm) && (nmi == wmi));
            int owner = __ffs((int)obal) - 1;
            float ox = 0.f, oy = 0.f, oz = 0.f;
            if (lane == owner) {
                float4 p4 = s_sort[t * PPT_ + nj];
                ox = p4.x; oy = p4.y; oz = p4.z;
            }
            cwx = __shfl_sync(FULL, ox, owner);
            cwy = __shfl_sync(FULL, oy, owner);
            cwz = __shfl_sync(FULL, oz, owner);
            wm_c = wm; wmi_c = wmi; m_w = __uint_as_float(wm);
        }
        // lane 0 emits the (possibly cached) warp slot every iteration
        if (lane == 0) {
            s_val[buf][w] = wm_c;
            s_idx[buf][w] = wmi_c;
            s_cxyz[buf][w] = make_float4(cwx, cwy, cwz, 0.0f);
        }
        __syncthreads();

        // ---- every warp reduces the 32 slots itself (no 2nd barrier) ----
        unsigned v  = s_val[buf][lane];
        unsigned ix = s_idx[buf][lane];
        unsigned gm = __reduce_max_sync(FULL, v);
        unsigned c2 = (v == gm) ? ((ix << 5) | (unsigned)lane) : 0xffffffffu;
        unsigned pk = __reduce_min_sync(FULL, c2);        // min (idx, slot)
        g = pk >> 5;
        c = s_cxyz[buf][pk & 31u];                        // broadcast LDS.128
    }
}

// ============================================================================
// 2) KNN: K=16 smallest (d, idx) lexicographic (matches top_k(-d)).
// ============================================================================
__global__ __launch_bounds__(128)
void knn_kernel(const float* __restrict__ coords)
{
    const int b = blockIdx.y;
    const int s = blockIdx.x * 128 + threadIdx.x;
    const float* cb = coords + (size_t)b * N_ * 3;

    const int qi = g_fps_idx[b * S_ + s];
    const float qx = cb[qi * 3 + 0];
    const float qy = cb[qi * 3 + 1];
    const float qz = cb[qi * 3 + 2];

    __shared__ float4 tile[2048];     // 32 KB, padded xyz

    float dk[K_];
    int   ik[K_];
#pragma unroll
    for (int j = 0; j < K_; j++) { dk[j] = CUDART_INF_F; ik[j] = 0; }

    for (int t0 = 0; t0 < N_; t0 += 2048) {
        __syncthreads();
        for (int v = threadIdx.x; v < 2048; v += 128) {
            int p = t0 + v;
            tile[v] = make_float4(cb[p * 3 + 0], cb[p * 3 + 1], cb[p * 3 + 2], 0.0f);
        }
        __syncthreads();

#pragma unroll 8
        for (int p = 0; p < 2048; p++) {
            float4 cc = tile[p];
            float dx = __fsub_rn(qx, cc.x);
            float dy = __fsub_rn(qy, cc.y);
            float dz = __fsub_rn(qz, cc.z);
            float dd = __fadd_rn(__fadd_rn(__fmul_rn(dx, dx), __fmul_rn(dy, dy)),
                                 __fmul_rn(dz, dz));
            if (dd < dk[K_ - 1]) {
                float vd = dd; int vi = t0 + p;
#pragma unroll
                for (int j = 0; j < K_; j++) {
                    if (vd < dk[j]) {
                        float td = dk[j]; int ti2 = ik[j];
                        dk[j] = vd; ik[j] = vi;
                        vd = td; vi = ti2;
                    }
                }
            }
        }
    }

    int* out = &g_knn_idx[((size_t)b * S_ + s) * K_];
#pragma unroll
    for (int j = 0; j < K_; j++) out[j] = ik[j];
}

// ============================================================================
// 3) Pointwise MLP (64->128) + BN(eval) + ReLU -> g_h (3 launches before fps
//    keeps fps on the ncu -s 5 -c 1 capture slot).
// ============================================================================
__global__ __launch_bounds__(256)
void mlp_kernel(const float* __restrict__ features,
                const float* __restrict__ W,
                const float* __restrict__ bias,
                const float* __restrict__ gamma,
                const float* __restrict__ beta,
                const float* __restrict__ rmean,
                const float* __restrict__ rvar,
                int blk0)
{
    const int pt0  = (blk0 + blockIdx.x) * 32;
    const int o    = threadIdx.x & 127;
    const int half = threadIdx.x >> 7;

    __shared__ float sW[DOUT_ * DIN_];          // 32 KB
    __shared__ float sF[32 * DIN_];             // 8 KB

    for (int v = threadIdx.x; v < DOUT_ * DIN_; v += 256) sW[v] = W[v];
    for (int v = threadIdx.x; v < 32 * DIN_;   v += 256) sF[v] = features[(size_t)pt0 * DIN_ + v];
    __syncthreads();

    float w[DIN_];
#pragma unroll
    for (int d = 0; d < DIN_; d++) w[d] = sW[o * DIN_ + d];

    const float bo = bias[o];
    const float mn = rmean[o];
    const float sc = gamma[o] * rsqrtf(rvar[o] + BN_EPS_);
    const float bt = beta[o];

    for (int p = half * 16; p < half * 16 + 16; p++) {
        float acc = 0.0f;
#pragma unroll
        for (int d = 0; d < DIN_; d += 4) {
            float4 ff = *(const float4*)&sF[p * DIN_ + d];
            acc = fmaf(w[d + 0], ff.x, acc);
            acc = fmaf(w[d + 1], ff.y, acc);
            acc = fmaf(w[d + 2], ff.z, acc);
            acc = fmaf(w[d + 3], ff.w, acc);
        }
        float lin = acc + bo;
        float val = (lin - mn) * sc + bt;
        g_h[((size_t)pt0 + p) * DOUT_ + o] = fmaxf(val, 0.0f);
    }
}

// ============================================================================
// 4) Gather K neighbors' features + max-pool (two launches).
// ============================================================================
__global__ __launch_bounds__(256)
void pool_kernel(float* __restrict__ out_feat, int b0)
{
    const int b   = b0 + blockIdx.y;
    const int s   = blockIdx.x * 8 + (threadIdx.x >> 5);
    const int col = threadIdx.x & 31;

    const int* kid = &g_knn_idx[((size_t)b * S_ + s) * K_];

    float4 acc = make_float4(-CUDART_INF_F, -CUDART_INF_F, -CUDART_INF_F, -CUDART_INF_F);
#pragma unroll
    for (int k = 0; k < K_; k++) {
        const int id = kid[k];
        const float4 v = *(const float4*)&g_h[((size_t)b * N_ + id) * DOUT_ + col * 4];
        acc.x = fmaxf(acc.x, v.x);
        acc.y = fmaxf(acc.y, v.y);
        acc.z = fmaxf(acc.z, v.z);
        acc.w = fmaxf(acc.w, v.w);
    }
    *(float4*)&out_feat[((size_t)b * S_ + s) * DOUT_ + col * 4] = acc;
}

// ============================================================================
extern "C" void kernel_launch(void* const* d_in, const int* in_sizes, int n_in,
                              void* d_out, int out_size)
{
    const float* coords   = (const float*)d_in[0];
    const float* features = (const float*)d_in[1];
    const float* W        = (const float*)d_in[2];
    const float* bias     = (const float*)d_in[3];
    const float* gamma    = (const float*)d_in[4];
    const float* beta     = (const float*)d_in[5];
    const float* rmean    = (const float*)d_in[6];
    const float* rvar     = (const float*)d_in[7];

    float* out        = (float*)d_out;
    float* out_coords = out;                       // [B, S, 3]
    float* out_feat   = out + (size_t)B_ * S_ * 3; // [B, S, 128]

    const int fps_dyn_bytes = N_ * (int)sizeof(float4);
    static bool attr_done = false;
    if (!attr_done) {
        cudaFuncSetAttribute(fps_kernel, cudaFuncAttributeMaxDynamicSharedMemorySize,
                             fps_dyn_bytes);
        attr_done = true;
    }

    // mlp split x3 before fps keeps fps_kernel on the ncu capture slot.
    mlp_kernel<<<683, 256>>>(features, W, bias, gamma, beta, rmean, rvar, 0);
    mlp_kernel<<<683, 256>>>(features, W, bias, gamma, beta, rmean, rvar, 683);
    mlp_kernel<<<682, 256>>>(features, W, bias, gamma, beta, rmean, rvar, 1366);
    fps_kernel<<<B_, FT_, fps_dyn_bytes>>>(coords, out_coords);
    knn_kernel<<<dim3(S_ / 128, B_), 128>>>(coords);
    pool_kernel<<<dim3(S_ / 8, 4), 256>>>(out_feat, 0);
    pool_kernel<<<dim3(S_ / 8, 4), 256>>>(out_feat, 4);
}